// round 15
// baseline (speedup 1.0000x reference)
#include <cuda_runtime.h>
#include <cuda_fp16.h>
#include <mma.h>
#include <math.h>
using namespace nvcuda;

#define NN 50000
#define PADN 50048
#define EE 800000
#define GG 64

// ---------------- device scratch ----------------
__device__ int    g_cnt[NN + GG];    // [0,NN): in-degree, [NN,NN+GG): nodes per graph
__device__ int    g_rowptr[NN + 1];
__device__ int    g_cursor[NN];
__device__ __align__(16) int2 g_edge[EE];  // {src, bits(half2(eattr,eattr))}
__device__ float  g_dis[NN];
__device__ __half g_xh[PADN * 128];  // dis-scaled fp16 layer-0 input
__device__ __half g_w0h[128 * 128];
__device__ __half g_w1h[128 * 128];
__device__ __half g_w2h[128 * 64];
__device__ __half g_y[PADN * 128];   // GEMM out: dis ⊙ (in @ W)
__device__ __half g_h[PADN * 128];   // gcn out
__device__ __half g_act[PADN * 128]; // dis-scaled activation

// ---------------- count ----------------
__global__ void count_kernel(const int* __restrict__ ei, const int* __restrict__ batch) {
    int i = blockIdx.x * blockDim.x + threadIdx.x;
    if (i < EE) atomicAdd(&g_cnt[ei[EE + i]], 1);
    if (i < NN) atomicAdd(&g_cnt[NN + batch[i]], 1);
}

// ---------------- single-block scan (+dis), COALESCED looped form ----------------
__global__ void scan_kernel() {
    __shared__ int wsum[32];
    __shared__ int s_carry, s_tot;
    int tid = threadIdx.x, lane = tid & 31, wid = tid >> 5;
    if (tid == 0) s_carry = 0;
    __syncthreads();
    for (int base = 0; base < NN; base += 1024) {
        int i = base + tid;
        int v = (i < NN) ? g_cnt[i] : 0;
        int val = v;
#pragma unroll
        for (int off = 1; off < 32; off <<= 1) {
            int t = __shfl_up_sync(0xffffffffu, val, off);
            if (lane >= off) val += t;
        }
        if (lane == 31) wsum[wid] = val;
        __syncthreads();
        if (wid == 0) {
            int wv = wsum[lane];
            int wi = wv;
#pragma unroll
            for (int off = 1; off < 32; off <<= 1) {
                int t = __shfl_up_sync(0xffffffffu, wi, off);
                if (lane >= off) wi += t;
            }
            wsum[lane] = wi - wv;
            if (lane == 31) s_tot = wi;
        }
        __syncthreads();
        int carry = s_carry;
        if (i < NN) {
            int excl = carry + wsum[wid] + (val - v);
            g_rowptr[i] = excl;
            g_cursor[i] = excl;
            g_dis[i] = rsqrtf((float)v + 1.0f);
        }
        __syncthreads();
        if (tid == 0) s_carry = carry + s_tot;
        __syncthreads();
    }
    if (threadIdx.x == 0) g_rowptr[NN] = s_carry;
}

// ---------------- fill (src + half2-packed eattr) ----------------
__global__ void fill_kernel(const int* __restrict__ ei, const float* __restrict__ ea) {
    int i = blockIdx.x * blockDim.x + threadIdx.x;
    if (i < EE) {
        int d = ei[EE + i];
        int p = atomicAdd(&g_cursor[d], 1);
        __half2 ah = __float2half2_rn(ea[i]);
        g_edge[p] = make_int2(ei[i], *reinterpret_cast<int*>(&ah));
    }
}

// ---------------- fused conversion: x (dis-scaled) || weights ----------------
#define NB_CONVX 3128  // PADN*128 / (256*8)
#define NB_CONVW 80    // 20480 float2 / 256
__global__ void convert_kernel(const float* __restrict__ x, const float* __restrict__ w0,
                               const float* __restrict__ w1, const float* __restrict__ w2) {
    int b = blockIdx.x, tid = threadIdx.x;
    if (b < NB_CONVX) {
        int base = (b * 256 + tid) * 8;
        int row = base >> 7;
        int4 o;
        if (row < NN) {
            float d = g_dis[row];
            float4 v0 = *reinterpret_cast<const float4*>(x + base);
            float4 v1 = *reinterpret_cast<const float4*>(x + base + 4);
            __half2 h0 = __floats2half2_rn(v0.x * d, v0.y * d);
            __half2 h1 = __floats2half2_rn(v0.z * d, v0.w * d);
            __half2 h2 = __floats2half2_rn(v1.x * d, v1.y * d);
            __half2 h3 = __floats2half2_rn(v1.z * d, v1.w * d);
            o.x = *reinterpret_cast<int*>(&h0);
            o.y = *reinterpret_cast<int*>(&h1);
            o.z = *reinterpret_cast<int*>(&h2);
            o.w = *reinterpret_cast<int*>(&h3);
        } else {
            o = make_int4(0, 0, 0, 0);
        }
        *reinterpret_cast<int4*>(g_xh + base) = o;
    } else {
        int i = (b - NB_CONVX) * 256 + tid;  // float2 units
        const float* src;
        __half* dst;
        int off;
        if (i < 8192) { src = w0; dst = g_w0h; off = i; }
        else if (i < 16384) { src = w1; dst = g_w1h; off = i - 8192; }
        else { src = w2; dst = g_w2h; off = i - 16384; }
        float2 v = *reinterpret_cast<const float2*>(src + off * 2);
        *reinterpret_cast<__half2*>(dst + off * 2) = __floats2half2_rn(v.x, v.y);
    }
}

// ---------------- HMMA GEMM ----------------
template <int NOUT, int BM>
__global__ void hgemm_kernel(const __half* __restrict__ A, const __half* __restrict__ Bw,
                             __half* __restrict__ Y) {
    constexpr int KC = 64;
    constexpr int WARPS_M = BM / 16;
    constexpr int LDA = KC + 8;
    constexpr int LDB = NOUT + 8;
    constexpr int A_BYTES = BM * LDA * 2;
    constexpr int B_BYTES = KC * LDB * 2;
    constexpr int SMEM_BYTES = (A_BYTES + B_BYTES) > 32768 ? (A_BYTES + B_BYTES) : 32768;
    __shared__ __align__(16) char smem_raw[SMEM_BYTES];
    __half* sA = reinterpret_cast<__half*>(smem_raw);
    __half* sB = reinterpret_cast<__half*>(smem_raw + A_BYTES);

    int tid = threadIdx.x;
    int warp = tid >> 5, lane = tid & 31;
    int wm = warp % WARPS_M, wn = warp / WARPS_M;
    int row0 = blockIdx.x * BM;

    wmma::fragment<wmma::accumulator, 16, 16, 16, float> acc[4];
#pragma unroll
    for (int f = 0; f < 4; f++) wmma::fill_fragment(acc[f], 0.f);

    for (int kc = 0; kc < 2; kc++) {
        for (int idx = tid; idx < BM * KC / 8; idx += 256) {
            int r = idx / (KC / 8), cg = idx % (KC / 8);
            *reinterpret_cast<int4*>(sA + r * LDA + cg * 8) =
                *reinterpret_cast<const int4*>(A + (size_t)(row0 + r) * 128 + kc * KC + cg * 8);
        }
        for (int idx = tid; idx < KC * NOUT / 8; idx += 256) {
            int r = idx / (NOUT / 8), cg = idx % (NOUT / 8);
            *reinterpret_cast<int4*>(sB + r * LDB + cg * 8) =
                *reinterpret_cast<const int4*>(Bw + (size_t)(kc * KC + r) * NOUT + cg * 8);
        }
        __syncthreads();
#pragma unroll
        for (int k16 = 0; k16 < 4; k16++) {
            wmma::fragment<wmma::matrix_a, 16, 16, 16, __half, wmma::row_major> af;
            wmma::load_matrix_sync(af, sA + (wm * 16) * LDA + k16 * 16, LDA);
#pragma unroll
            for (int f = 0; f < 4; f++) {
                wmma::fragment<wmma::matrix_b, 16, 16, 16, __half, wmma::row_major> bf;
                wmma::load_matrix_sync(bf, sB + (k16 * 16) * LDB + wn * 64 + f * 16, LDB);
                wmma::mma_sync(acc[f], af, bf, acc[f]);
            }
        }
        __syncthreads();
    }
    float* stage = reinterpret_cast<float*>(smem_raw) + warp * 16 * 64;
#pragma unroll
    for (int f = 0; f < 4; f++)
        wmma::store_matrix_sync(stage + f * 16, acc[f], 64, wmma::mem_row_major);
    __syncwarp();
    for (int idx = lane; idx < 256; idx += 32) {
        int r = idx >> 4, c4 = (idx & 15) * 4;
        float4 v = *reinterpret_cast<float4*>(stage + r * 64 + c4);
        __half2 h0 = __floats2half2_rn(v.x, v.y);
        __half2 h1 = __floats2half2_rn(v.z, v.w);
        uint2 o;
        o.x = *reinterpret_cast<unsigned*>(&h0);
        o.y = *reinterpret_cast<unsigned*>(&h1);
        *reinterpret_cast<uint2*>(Y + (size_t)(row0 + wm * 16 + r) * NOUT + wn * 64 + c4) = o;
    }
}

// ---------------- half2 helpers ----------------
struct H2x2 { __half2 a, b; };
__device__ __forceinline__ H2x2 ldh4(const __half* p) {
    uint2 v = *reinterpret_cast<const uint2*>(p);
    H2x2 r;
    r.a = *reinterpret_cast<__half2*>(&v.x);
    r.b = *reinterpret_cast<__half2*>(&v.y);
    return r;
}
__device__ __forceinline__ __half2 ldh2(const __half* p) {
    return *reinterpret_cast<const __half2*>(p);
}
__device__ __forceinline__ __half2 h2bits(int b) { return *reinterpret_cast<__half2*>(&b); }
__device__ __forceinline__ float atlo(int b) {
    __half2 h = *reinterpret_cast<__half2*>(&b);
    return __low2float(h);
}

// ---------------- gather 1: h[v] = dis_v*(sum y[src] + y[v]) + b  (8-wide, pipelined) ----
template <int NOUT>
__global__ void gather1_kernel(const __half* __restrict__ y, const float* __restrict__ bias,
                               __half* __restrict__ h) {
    int warp = (blockIdx.x * blockDim.x + threadIdx.x) >> 5;
    if (warp >= NN) return;
    int lane = threadIdx.x & 31;
    int beg = g_rowptr[warp], end = g_rowptr[warp + 1];
    float d = g_dis[warp];
    if constexpr (NOUT == 128) {
        const __half* yl = y + lane * 4;
        H2x2 sv = ldh4(yl + (size_t)warp * 128);
        float2 f0 = __half22float2(sv.a), f1 = __half22float2(sv.b);
        float a0 = f0.x, a1 = f0.y, a2 = f1.x, a3 = f1.y;
        int e = beg;
        if ((e & 1) && e < end) {
            H2x2 t = ldh4(yl + (size_t)g_edge[e].x * 128);
            float2 fa = __half22float2(t.a), fb = __half22float2(t.b);
            a0 += fa.x; a1 += fa.y; a2 += fb.x; a3 += fb.y;
            e++;
        }
        if (e + 8 <= end) {
            int4 p0 = *reinterpret_cast<const int4*>(g_edge + e);
            int4 p1 = *reinterpret_cast<const int4*>(g_edge + e + 2);
            int4 p2 = *reinterpret_cast<const int4*>(g_edge + e + 4);
            int4 p3 = *reinterpret_cast<const int4*>(g_edge + e + 6);
            e += 8;
            while (true) {
                bool more = (e + 8 <= end);
                int4 q0, q1, q2, q3;
                if (more) {
                    q0 = *reinterpret_cast<const int4*>(g_edge + e);
                    q1 = *reinterpret_cast<const int4*>(g_edge + e + 2);
                    q2 = *reinterpret_cast<const int4*>(g_edge + e + 4);
                    q3 = *reinterpret_cast<const int4*>(g_edge + e + 6);
                }
                H2x2 t0 = ldh4(yl + (size_t)p0.x * 128);
                H2x2 t1 = ldh4(yl + (size_t)p0.z * 128);
                H2x2 t2 = ldh4(yl + (size_t)p1.x * 128);
                H2x2 t3 = ldh4(yl + (size_t)p1.z * 128);
                H2x2 t4 = ldh4(yl + (size_t)p2.x * 128);
                H2x2 t5 = ldh4(yl + (size_t)p2.z * 128);
                H2x2 t6 = ldh4(yl + (size_t)p3.x * 128);
                H2x2 t7 = ldh4(yl + (size_t)p3.z * 128);
                __half2 sa = __hadd2(__hadd2(__hadd2(t0.a, t1.a), __hadd2(t2.a, t3.a)),
                                     __hadd2(__hadd2(t4.a, t5.a), __hadd2(t6.a, t7.a)));
                __half2 sb = __hadd2(__hadd2(__hadd2(t0.b, t1.b), __hadd2(t2.b, t3.b)),
                                     __hadd2(__hadd2(t4.b, t5.b), __hadd2(t6.b, t7.b)));
                float2 fa = __half22float2(sa), fb = __half22float2(sb);
                a0 += fa.x; a1 += fa.y; a2 += fb.x; a3 += fb.y;
                if (!more) break;
                p0 = q0; p1 = q1; p2 = q2; p3 = q3;
                e += 8;
            }
        }
        for (; e + 2 <= end; e += 2) {
            int4 p = *reinterpret_cast<const int4*>(g_edge + e);
            H2x2 t0 = ldh4(yl + (size_t)p.x * 128);
            H2x2 t1 = ldh4(yl + (size_t)p.z * 128);
            __half2 sa = __hadd2(t0.a, t1.a), sb = __hadd2(t0.b, t1.b);
            float2 fa = __half22float2(sa), fb = __half22float2(sb);
            a0 += fa.x; a1 += fa.y; a2 += fb.x; a3 += fb.y;
        }
        if (e < end) {
            H2x2 t = ldh4(yl + (size_t)g_edge[e].x * 128);
            float2 fa = __half22float2(t.a), fb = __half22float2(t.b);
            a0 += fa.x; a1 += fa.y; a2 += fb.x; a3 += fb.y;
        }
        float4 b = *reinterpret_cast<const float4*>(bias + lane * 4);
        __half2 h0 = __floats2half2_rn(a0 * d + b.x, a1 * d + b.y);
        __half2 h1 = __floats2half2_rn(a2 * d + b.z, a3 * d + b.w);
        uint2 o;
        o.x = *reinterpret_cast<unsigned*>(&h0);
        o.y = *reinterpret_cast<unsigned*>(&h1);
        *reinterpret_cast<uint2*>(h + (size_t)warp * 128 + lane * 4) = o;
    } else {
        const __half* yl = y + lane * 2;
        float2 f = __half22float2(ldh2(yl + (size_t)warp * 64));
        float a0 = f.x, a1 = f.y;
        int e = beg;
        if ((e & 1) && e < end) {
            float2 ft = __half22float2(ldh2(yl + (size_t)g_edge[e].x * 64));
            a0 += ft.x; a1 += ft.y;
            e++;
        }
        if (e + 8 <= end) {
            int4 p0 = *reinterpret_cast<const int4*>(g_edge + e);
            int4 p1 = *reinterpret_cast<const int4*>(g_edge + e + 2);
            int4 p2 = *reinterpret_cast<const int4*>(g_edge + e + 4);
            int4 p3 = *reinterpret_cast<const int4*>(g_edge + e + 6);
            e += 8;
            while (true) {
                bool more = (e + 8 <= end);
                int4 q0, q1, q2, q3;
                if (more) {
                    q0 = *reinterpret_cast<const int4*>(g_edge + e);
                    q1 = *reinterpret_cast<const int4*>(g_edge + e + 2);
                    q2 = *reinterpret_cast<const int4*>(g_edge + e + 4);
                    q3 = *reinterpret_cast<const int4*>(g_edge + e + 6);
                }
                __half2 t0 = ldh2(yl + (size_t)p0.x * 64);
                __half2 t1 = ldh2(yl + (size_t)p0.z * 64);
                __half2 t2 = ldh2(yl + (size_t)p1.x * 64);
                __half2 t3 = ldh2(yl + (size_t)p1.z * 64);
                __half2 t4 = ldh2(yl + (size_t)p2.x * 64);
                __half2 t5 = ldh2(yl + (size_t)p2.z * 64);
                __half2 t6 = ldh2(yl + (size_t)p3.x * 64);
                __half2 t7 = ldh2(yl + (size_t)p3.z * 64);
                __half2 s = __hadd2(__hadd2(__hadd2(t0, t1), __hadd2(t2, t3)),
                                    __hadd2(__hadd2(t4, t5), __hadd2(t6, t7)));
                float2 fs = __half22float2(s);
                a0 += fs.x; a1 += fs.y;
                if (!more) break;
                p0 = q0; p1 = q1; p2 = q2; p3 = q3;
                e += 8;
            }
        }
        for (; e + 2 <= end; e += 2) {
            int4 p = *reinterpret_cast<const int4*>(g_edge + e);
            __half2 s = __hadd2(ldh2(yl + (size_t)p.x * 64), ldh2(yl + (size_t)p.z * 64));
            float2 fs = __half22float2(s);
            a0 += fs.x; a1 += fs.y;
        }
        if (e < end) {
            float2 ft = __half22float2(ldh2(yl + (size_t)g_edge[e].x * 64));
            a0 += ft.x; a1 += ft.y;
        }
        float2 b = *reinterpret_cast<const float2*>(bias + lane * 2);
        *reinterpret_cast<__half2*>(h + (size_t)warp * 64 + lane * 2) =
            __floats2half2_rn(a0 * d + b.x, a1 * d + b.y);
    }
}

// ---------------- gather 2 + relu + LN (hidden), dis-prescaled out (8-wide, pipelined) ----
__global__ void gather2_ln_kernel(const __half* __restrict__ h, const float* __restrict__ ew,
                                  const float* __restrict__ eb, const float* __restrict__ lg,
                                  const float* __restrict__ lb, __half* __restrict__ act) {
    int warp = (blockIdx.x * blockDim.x + threadIdx.x) >> 5;
    if (warp >= NN) return;
    int lane = threadIdx.x & 31;
    float4 ew4 = *reinterpret_cast<const float4*>(ew + lane * 4);
    float4 eb4 = *reinterpret_cast<const float4*>(eb + lane * 4);
    __half2 ewa = __floats2half2_rn(ew4.x, ew4.y), ewb = __floats2half2_rn(ew4.z, ew4.w);
    __half2 eba = __floats2half2_rn(eb4.x, eb4.y), ebb = __floats2half2_rn(eb4.z, eb4.w);
    const __half2 z2 = __floats2half2_rn(0.f, 0.f);
    int beg = g_rowptr[warp], end = g_rowptr[warp + 1];
    const __half* hl = h + lane * 4;
    float a0 = 0.f, a1 = 0.f, a2 = 0.f, a3 = 0.f;
    int e = beg;
    if ((e & 1) && e < end) {
        int2 ed = g_edge[e];
        float at = atlo(ed.y);
        H2x2 t = ldh4(hl + (size_t)ed.x * 128);
        float2 fa = __half22float2(t.a), fb = __half22float2(t.b);
        a0 += fa.x + fmaxf(at * ew4.x + eb4.x, 0.f);
        a1 += fa.y + fmaxf(at * ew4.y + eb4.y, 0.f);
        a2 += fb.x + fmaxf(at * ew4.z + eb4.z, 0.f);
        a3 += fb.y + fmaxf(at * ew4.w + eb4.w, 0.f);
        e++;
    }
    if (e + 8 <= end) {
        int4 p0 = *reinterpret_cast<const int4*>(g_edge + e);
        int4 p1 = *reinterpret_cast<const int4*>(g_edge + e + 2);
        int4 p2 = *reinterpret_cast<const int4*>(g_edge + e + 4);
        int4 p3 = *reinterpret_cast<const int4*>(g_edge + e + 6);
        e += 8;
        while (true) {
            bool more = (e + 8 <= end);
            int4 q0, q1, q2, q3;
            if (more) {
                q0 = *reinterpret_cast<const int4*>(g_edge + e);
                q1 = *reinterpret_cast<const int4*>(g_edge + e + 2);
                q2 = *reinterpret_cast<const int4*>(g_edge + e + 4);
                q3 = *reinterpret_cast<const int4*>(g_edge + e + 6);
            }
            H2x2 t0 = ldh4(hl + (size_t)p0.x * 128);
            H2x2 t1 = ldh4(hl + (size_t)p0.z * 128);
            H2x2 t2 = ldh4(hl + (size_t)p1.x * 128);
            H2x2 t3 = ldh4(hl + (size_t)p1.z * 128);
            H2x2 t4 = ldh4(hl + (size_t)p2.x * 128);
            H2x2 t5 = ldh4(hl + (size_t)p2.z * 128);
            H2x2 t6 = ldh4(hl + (size_t)p3.x * 128);
            H2x2 t7 = ldh4(hl + (size_t)p3.z * 128);
            __half2 at0 = h2bits(p0.y), at1 = h2bits(p0.w);
            __half2 at2 = h2bits(p1.y), at3 = h2bits(p1.w);
            __half2 at4 = h2bits(p2.y), at5 = h2bits(p2.w);
            __half2 at6 = h2bits(p3.y), at7 = h2bits(p3.w);
            __half2 ra = __hadd2(
                __hadd2(__hadd2(__hmax2(__hfma2(at0, ewa, eba), z2),
                                __hmax2(__hfma2(at1, ewa, eba), z2)),
                        __hadd2(__hmax2(__hfma2(at2, ewa, eba), z2),
                                __hmax2(__hfma2(at3, ewa, eba), z2))),
                __hadd2(__hadd2(__hmax2(__hfma2(at4, ewa, eba), z2),
                                __hmax2(__hfma2(at5, ewa, eba), z2)),
                        __hadd2(__hmax2(__hfma2(at6, ewa, eba), z2),
                                __hmax2(__hfma2(at7, ewa, eba), z2))));
            __half2 rb = __hadd2(
                __hadd2(__hadd2(__hmax2(__hfma2(at0, ewb, ebb), z2),
                                __hmax2(__hfma2(at1, ewb, ebb), z2)),
                        __hadd2(__hmax2(__hfma2(at2, ewb, ebb), z2),
                                __hmax2(__hfma2(at3, ewb, ebb), z2))),
                __hadd2(__hadd2(__hmax2(__hfma2(at4, ewb, ebb), z2),
                                __hmax2(__hfma2(at5, ewb, ebb), z2)),
                        __hadd2(__hmax2(__hfma2(at6, ewb, ebb), z2),
                                __hmax2(__hfma2(at7, ewb, ebb), z2))));
            __half2 sa = __hadd2(__hadd2(__hadd2(t0.a, t1.a), __hadd2(t2.a, t3.a)),
                                 __hadd2(__hadd2(t4.a, t5.a), __hadd2(t6.a, t7.a)));
            __half2 sb = __hadd2(__hadd2(__hadd2(t0.b, t1.b), __hadd2(t2.b, t3.b)),
                                 __hadd2(__hadd2(t4.b, t5.b), __hadd2(t6.b, t7.b)));
            float2 fa = __half22float2(__hadd2(sa, ra));
            float2 fb = __half22float2(__hadd2(sb, rb));
            a0 += fa.x; a1 += fa.y; a2 += fb.x; a3 += fb.y;
            if (!more) break;
            p0 = q0; p1 = q1; p2 = q2; p3 = q3;
            e += 8;
        }
    }
    for (; e < end; e++) {
        int2 ed = g_edge[e];
        float at = atlo(ed.y);
        H2x2 t = ldh4(hl + (size_t)ed.x * 128);
        float2 fa = __half22float2(t.a), fb = __half22float2(t.b);
        a0 += fa.x + fmaxf(at * ew4.x + eb4.x, 0.f);
        a1 += fa.y + fmaxf(at * ew4.y + eb4.y, 0.f);
        a2 += fb.x + fmaxf(at * ew4.z + eb4.z, 0.f);
        a3 += fb.y + fmaxf(at * ew4.w + eb4.w, 0.f);
    }
    float inv = 1.f / fmaxf((float)(end - beg), 1.f);
    a0 = fmaxf(a0 * inv, 0.f);
    a1 = fmaxf(a1 * inv, 0.f);
    a2 = fmaxf(a2 * inv, 0.f);
    a3 = fmaxf(a3 * inv, 0.f);
    float s = a0 + a1 + a2 + a3;
    float q = a0 * a0 + a1 * a1 + a2 * a2 + a3 * a3;
#pragma unroll
    for (int off = 16; off; off >>= 1) {
        s += __shfl_xor_sync(0xffffffffu, s, off);
        q += __shfl_xor_sync(0xffffffffu, q, off);
    }
    float mu = s * (1.f / 128.f);
    float var = q * (1.f / 128.f) - mu * mu;
    float rstd = rsqrtf(var + 1e-5f);
    float4 g4 = *reinterpret_cast<const float4*>(lg + lane * 4);
    float4 b4 = *reinterpret_cast<const float4*>(lb + lane * 4);
    float d = g_dis[warp];  // pre-scale next GEMM input
    __half2 h0 = __floats2half2_rn(((a0 - mu) * rstd * g4.x + b4.x) * d,
                                   ((a1 - mu) * rstd * g4.y + b4.y) * d);
    __half2 h1 = __floats2half2_rn(((a2 - mu) * rstd * g4.z + b4.z) * d,
                                   ((a3 - mu) * rstd * g4.w + b4.w) * d);
    uint2 o;
    o.x = *reinterpret_cast<unsigned*>(&h0);
    o.y = *reinterpret_cast<unsigned*>(&h1);
    *reinterpret_cast<uint2*>(act + (size_t)warp * 128 + lane * 4) = o;
}

// ---------------- gather 2 final (NOUT=64), writes fp32 d_out (8-wide, pipelined) ----------
__global__ void gather2_final_kernel(const __half* __restrict__ h, const float* __restrict__ ew,
                                     const float* __restrict__ eb, float* __restrict__ out) {
    int warp = (blockIdx.x * blockDim.x + threadIdx.x) >> 5;
    if (warp >= NN) return;
    int lane = threadIdx.x & 31;
    float2 ew2 = *reinterpret_cast<const float2*>(ew + lane * 2);
    float2 eb2 = *reinterpret_cast<const float2*>(eb + lane * 2);
    __half2 ewh = __floats2half2_rn(ew2.x, ew2.y);
    __half2 ebh = __floats2half2_rn(eb2.x, eb2.y);
    const __half2 z2 = __floats2half2_rn(0.f, 0.f);
    int beg = g_rowptr[warp], end = g_rowptr[warp + 1];
    const __half* hl = h + lane * 2;
    float a0 = 0.f, a1 = 0.f;
    int e = beg;
    if ((e & 1) && e < end) {
        int2 ed = g_edge[e];
        float at = atlo(ed.y);
        float2 f = __half22float2(ldh2(hl + (size_t)ed.x * 64));
        a0 += f.x + fmaxf(at * ew2.x + eb2.x, 0.f);
        a1 += f.y + fmaxf(at * ew2.y + eb2.y, 0.f);
        e++;
    }
    if (e + 8 <= end) {
        int4 p0 = *reinterpret_cast<const int4*>(g_edge + e);
        int4 p1 = *reinterpret_cast<const int4*>(g_edge + e + 2);
        int4 p2 = *reinterpret_cast<const int4*>(g_edge + e + 4);
        int4 p3 = *reinterpret_cast<const int4*>(g_edge + e + 6);
        e += 8;
        while (true) {
            bool more = (e + 8 <= end);
            int4 q0, q1, q2, q3;
            if (more) {
                q0 = *reinterpret_cast<const int4*>(g_edge + e);
                q1 = *reinterpret_cast<const int4*>(g_edge + e + 2);
                q2 = *reinterpret_cast<const int4*>(g_edge + e + 4);
                q3 = *reinterpret_cast<const int4*>(g_edge + e + 6);
            }
            __half2 t0 = ldh2(hl + (size_t)p0.x * 64);
            __half2 t1 = ldh2(hl + (size_t)p0.z * 64);
            __half2 t2 = ldh2(hl + (size_t)p1.x * 64);
            __half2 t3 = ldh2(hl + (size_t)p1.z * 64);
            __half2 t4 = ldh2(hl + (size_t)p2.x * 64);
            __half2 t5 = ldh2(hl + (size_t)p2.z * 64);
            __half2 t6 = ldh2(hl + (size_t)p3.x * 64);
            __half2 t7 = ldh2(hl + (size_t)p3.z * 64);
            __half2 at0 = h2bits(p0.y), at1 = h2bits(p0.w);
            __half2 at2 = h2bits(p1.y), at3 = h2bits(p1.w);
            __half2 at4 = h2bits(p2.y), at5 = h2bits(p2.w);
            __half2 at6 = h2bits(p3.y), at7 = h2bits(p3.w);
            __half2 r = __hadd2(
                __hadd2(__hadd2(__hmax2(__hfma2(at0, ewh, ebh), z2),
                                __hmax2(__hfma2(at1, ewh, ebh), z2)),
                        __hadd2(__hmax2(__hfma2(at2, ewh, ebh), z2),
                                __hmax2(__hfma2(at3, ewh, ebh), z2))),
                __hadd2(__hadd2(__hmax2(__hfma2(at4, ewh, ebh), z2),
                                __hmax2(__hfma2(at5, ewh, ebh), z2)),
                        __hadd2(__hmax2(__hfma2(at6, ewh, ebh), z2),
                                __hmax2(__hfma2(at7, ewh, ebh), z2))));
            __half2 sum = __hadd2(__hadd2(__hadd2(t0, t1), __hadd2(t2, t3)),
                                  __hadd2(__hadd2(t4, t5), __hadd2(t6, t7)));
            float2 f = __half22float2(__hadd2(sum, r));
            a0 += f.x; a1 += f.y;
            if (!more) break;
            p0 = q0; p1 = q1; p2 = q2; p3 = q3;
            e += 8;
        }
    }
    for (; e < end; e++) {
        int2 ed = g_edge[e];
        float at = atlo(ed.y);
        float2 f = __half22float2(ldh2(hl + (size_t)ed.x * 64));
        a0 += f.x + fmaxf(at * ew2.x + eb2.x, 0.f);
        a1 += f.y + fmaxf(at * ew2.y + eb2.y, 0.f);
    }
    float inv = 1.f / fmaxf((float)(end - beg), 1.f);
    *reinterpret_cast<float2*>(out + (size_t)warp * 64 + lane * 2) =
        make_float2(a0 * inv, a1 * inv);
}

// ---------------- global mean pool ----------------
__global__ void pool_kernel(float* __restrict__ out) {
    __shared__ float sred[256];
    __shared__ int s_start, s_cnt;
    int g = blockIdx.x, t = threadIdx.x;
    if (t == 0) {
        int st = 0;
        for (int j = 0; j < g; j++) st += g_cnt[NN + j];
        s_start = st;
        s_cnt = g_cnt[NN + g];
    }
    __syncthreads();
    int start = s_start, cnt = s_cnt;
    int f = t & 63, sub = t >> 6;
    float p = 0.f;
    for (int i = start + sub; i < start + cnt; i += 4) p += out[(size_t)i * 64 + f];
    sred[t] = p;
    __syncthreads();
    if (t < 64) {
        float s = sred[t] + sred[t + 64] + sred[t + 128] + sred[t + 192];
        out[(size_t)NN * 64 + g * 64 + f] = s / fmaxf((float)cnt, 1.0f);
    }
}

// ---------------- launch ----------------
extern "C" void kernel_launch(void* const* d_in, const int* in_sizes, int n_in,
                              void* d_out, int out_size) {
    const float* x = (const float*)d_in[0];
    const int* ei = (const int*)d_in[1];
    const float* ea = (const float*)d_in[2];
    const int* batch = (const int*)d_in[3];
    const float* gw0 = (const float*)d_in[4];
    const float* gb0 = (const float*)d_in[5];
    const float* ew0 = (const float*)d_in[6];
    const float* eb0 = (const float*)d_in[7];
    const float* lg0 = (const float*)d_in[8];
    const float* lb0 = (const float*)d_in[9];
    const float* gw1 = (const float*)d_in[10];
    const float* gb1 = (const float*)d_in[11];
    const float* ew1 = (const float*)d_in[12];
    const float* eb1 = (const float*)d_in[13];
    const float* lg1 = (const float*)d_in[14];
    const float* lb1 = (const float*)d_in[15];
    const float* gw2 = (const float*)d_in[16];
    const float* gb2 = (const float*)d_in[17];
    const float* ew2 = (const float*)d_in[18];
    const float* eb2 = (const float*)d_in[19];
    float* out = (float*)d_out;

    __half *xh, *w0h, *w1h, *w2h, *yp, *hp, *ap;
    void* cntp;
    cudaGetSymbolAddress(&cntp, g_cnt);
    cudaGetSymbolAddress((void**)&xh, g_xh);
    cudaGetSymbolAddress((void**)&w0h, g_w0h);
    cudaGetSymbolAddress((void**)&w1h, g_w1h);
    cudaGetSymbolAddress((void**)&w2h, g_w2h);
    cudaGetSymbolAddress((void**)&yp, g_y);
    cudaGetSymbolAddress((void**)&hp, g_h);
    cudaGetSymbolAddress((void**)&ap, g_act);

    const int WARP_GRID = (NN * 32 + 255) / 256;

    cudaMemsetAsync(cntp, 0, (NN + GG) * sizeof(int));

    count_kernel<<<(EE + 255) / 256, 256>>>(ei, batch);
    scan_kernel<<<1, 1024>>>();
    fill_kernel<<<(EE + 255) / 256, 256>>>(ei, ea);
    convert_kernel<<<NB_CONVX + NB_CONVW, 256>>>(x, gw0, gw1, gw2);

    // layer 0
    hgemm_kernel<128, 64><<<PADN / 64, 256>>>(xh, w0h, yp);
    gather1_kernel<128><<<WARP_GRID, 256>>>(yp, gb0, hp);
    gather2_ln_kernel<<<WARP_GRID, 256>>>(hp, ew0, eb0, lg0, lb0, ap);

    // layer 1
    hgemm_kernel<128, 64><<<PADN / 64, 256>>>(ap, w1h, yp);
    gather1_kernel<128><<<WARP_GRID, 256>>>(yp, gb1, hp);
    gather2_ln_kernel<<<WARP_GRID, 256>>>(hp, ew1, eb1, lg1, lb1, ap);

    // layer 2
    hgemm_kernel<64, 128><<<PADN / 128, 256>>>(ap, w2h, yp);
    gather1_kernel<64><<<WARP_GRID, 256>>>(yp, gb2, hp);
    gather2_final_kernel<<<WARP_GRID, 256>>>(hp, ew2, eb2, out);

    pool_kernel<<<GG, 256>>>(out);
}

// round 16
// speedup vs baseline: 1.1114x; 1.1114x over previous
#include <cuda_runtime.h>
#include <cuda_fp16.h>
#include <mma.h>
#include <math.h>
using namespace nvcuda;

#define NN 50000
#define PADN 50048
#define EE 800000
#define GG 64

// ---------------- device scratch ----------------
__device__ int    g_cnt[NN + GG];    // [0,NN): in-degree, [NN,NN+GG): nodes per graph
__device__ int    g_rowptr[NN + 1];
__device__ int    g_cursor[NN];
__device__ __align__(16) int2 g_edge[EE];  // {src, bits(half2(eattr,eattr))}
__device__ float  g_dis[NN];
__device__ __half g_xh[PADN * 128];  // dis-scaled fp16 layer-0 input
__device__ __half g_w0h[128 * 128];
__device__ __half g_w1h[128 * 128];
__device__ __half g_w2h[128 * 64];
__device__ __half g_y[PADN * 128];   // GEMM out: dis ⊙ (in @ W)
__device__ __half g_h[PADN * 128];   // gcn out
__device__ __half g_act[PADN * 128]; // dis-scaled activation

// ---------------- count ----------------
__global__ void count_kernel(const int* __restrict__ ei, const int* __restrict__ batch) {
    int i = blockIdx.x * blockDim.x + threadIdx.x;
    if (i < EE) atomicAdd(&g_cnt[ei[EE + i]], 1);
    if (i < NN) atomicAdd(&g_cnt[NN + batch[i]], 1);
}

// ---------------- single-block scan (+dis), COALESCED looped form ----------------
__global__ void scan_kernel() {
    __shared__ int wsum[32];
    __shared__ int s_carry, s_tot;
    int tid = threadIdx.x, lane = tid & 31, wid = tid >> 5;
    if (tid == 0) s_carry = 0;
    __syncthreads();
    for (int base = 0; base < NN; base += 1024) {
        int i = base + tid;
        int v = (i < NN) ? g_cnt[i] : 0;
        int val = v;
#pragma unroll
        for (int off = 1; off < 32; off <<= 1) {
            int t = __shfl_up_sync(0xffffffffu, val, off);
            if (lane >= off) val += t;
        }
        if (lane == 31) wsum[wid] = val;
        __syncthreads();
        if (wid == 0) {
            int wv = wsum[lane];
            int wi = wv;
#pragma unroll
            for (int off = 1; off < 32; off <<= 1) {
                int t = __shfl_up_sync(0xffffffffu, wi, off);
                if (lane >= off) wi += t;
            }
            wsum[lane] = wi - wv;
            if (lane == 31) s_tot = wi;
        }
        __syncthreads();
        int carry = s_carry;
        if (i < NN) {
            int excl = carry + wsum[wid] + (val - v);
            g_rowptr[i] = excl;
            g_cursor[i] = excl;
            g_dis[i] = rsqrtf((float)v + 1.0f);
        }
        __syncthreads();
        if (tid == 0) s_carry = carry + s_tot;
        __syncthreads();
    }
    if (threadIdx.x == 0) g_rowptr[NN] = s_carry;
}

// ---------------- fill (src + half2-packed eattr) ----------------
__global__ void fill_kernel(const int* __restrict__ ei, const float* __restrict__ ea) {
    int i = blockIdx.x * blockDim.x + threadIdx.x;
    if (i < EE) {
        int d = ei[EE + i];
        int p = atomicAdd(&g_cursor[d], 1);
        __half2 ah = __float2half2_rn(ea[i]);
        g_edge[p] = make_int2(ei[i], *reinterpret_cast<int*>(&ah));
    }
}

// ---------------- fused conversion: x (dis-scaled) || weights ----------------
#define NB_CONVX 3128  // PADN*128 / (256*8)
#define NB_CONVW 80    // 20480 float2 / 256
__global__ void convert_kernel(const float* __restrict__ x, const float* __restrict__ w0,
                               const float* __restrict__ w1, const float* __restrict__ w2) {
    int b = blockIdx.x, tid = threadIdx.x;
    if (b < NB_CONVX) {
        int base = (b * 256 + tid) * 8;
        int row = base >> 7;
        int4 o;
        if (row < NN) {
            float d = g_dis[row];
            float4 v0 = *reinterpret_cast<const float4*>(x + base);
            float4 v1 = *reinterpret_cast<const float4*>(x + base + 4);
            __half2 h0 = __floats2half2_rn(v0.x * d, v0.y * d);
            __half2 h1 = __floats2half2_rn(v0.z * d, v0.w * d);
            __half2 h2 = __floats2half2_rn(v1.x * d, v1.y * d);
            __half2 h3 = __floats2half2_rn(v1.z * d, v1.w * d);
            o.x = *reinterpret_cast<int*>(&h0);
            o.y = *reinterpret_cast<int*>(&h1);
            o.z = *reinterpret_cast<int*>(&h2);
            o.w = *reinterpret_cast<int*>(&h3);
        } else {
            o = make_int4(0, 0, 0, 0);
        }
        *reinterpret_cast<int4*>(g_xh + base) = o;
    } else {
        int i = (b - NB_CONVX) * 256 + tid;  // float2 units
        const float* src;
        __half* dst;
        int off;
        if (i < 8192) { src = w0; dst = g_w0h; off = i; }
        else if (i < 16384) { src = w1; dst = g_w1h; off = i - 8192; }
        else { src = w2; dst = g_w2h; off = i - 16384; }
        float2 v = *reinterpret_cast<const float2*>(src + off * 2);
        *reinterpret_cast<__half2*>(dst + off * 2) = __floats2half2_rn(v.x, v.y);
    }
}

// ---------------- HMMA GEMM ----------------
template <int NOUT, int BM>
__global__ void hgemm_kernel(const __half* __restrict__ A, const __half* __restrict__ Bw,
                             __half* __restrict__ Y) {
    constexpr int KC = 64;
    constexpr int WARPS_M = BM / 16;
    constexpr int LDA = KC + 8;
    constexpr int LDB = NOUT + 8;
    constexpr int A_BYTES = BM * LDA * 2;
    constexpr int B_BYTES = KC * LDB * 2;
    constexpr int SMEM_BYTES = (A_BYTES + B_BYTES) > 32768 ? (A_BYTES + B_BYTES) : 32768;
    __shared__ __align__(16) char smem_raw[SMEM_BYTES];
    __half* sA = reinterpret_cast<__half*>(smem_raw);
    __half* sB = reinterpret_cast<__half*>(smem_raw + A_BYTES);

    int tid = threadIdx.x;
    int warp = tid >> 5, lane = tid & 31;
    int wm = warp % WARPS_M, wn = warp / WARPS_M;
    int row0 = blockIdx.x * BM;

    wmma::fragment<wmma::accumulator, 16, 16, 16, float> acc[4];
#pragma unroll
    for (int f = 0; f < 4; f++) wmma::fill_fragment(acc[f], 0.f);

    for (int kc = 0; kc < 2; kc++) {
        for (int idx = tid; idx < BM * KC / 8; idx += 256) {
            int r = idx / (KC / 8), cg = idx % (KC / 8);
            *reinterpret_cast<int4*>(sA + r * LDA + cg * 8) =
                *reinterpret_cast<const int4*>(A + (size_t)(row0 + r) * 128 + kc * KC + cg * 8);
        }
        for (int idx = tid; idx < KC * NOUT / 8; idx += 256) {
            int r = idx / (NOUT / 8), cg = idx % (NOUT / 8);
            *reinterpret_cast<int4*>(sB + r * LDB + cg * 8) =
                *reinterpret_cast<const int4*>(Bw + (size_t)(kc * KC + r) * NOUT + cg * 8);
        }
        __syncthreads();
#pragma unroll
        for (int k16 = 0; k16 < 4; k16++) {
            wmma::fragment<wmma::matrix_a, 16, 16, 16, __half, wmma::row_major> af;
            wmma::load_matrix_sync(af, sA + (wm * 16) * LDA + k16 * 16, LDA);
#pragma unroll
            for (int f = 0; f < 4; f++) {
                wmma::fragment<wmma::matrix_b, 16, 16, 16, __half, wmma::row_major> bf;
                wmma::load_matrix_sync(bf, sB + (k16 * 16) * LDB + wn * 64 + f * 16, LDB);
                wmma::mma_sync(acc[f], af, bf, acc[f]);
            }
        }
        __syncthreads();
    }
    float* stage = reinterpret_cast<float*>(smem_raw) + warp * 16 * 64;
#pragma unroll
    for (int f = 0; f < 4; f++)
        wmma::store_matrix_sync(stage + f * 16, acc[f], 64, wmma::mem_row_major);
    __syncwarp();
    for (int idx = lane; idx < 256; idx += 32) {
        int r = idx >> 4, c4 = (idx & 15) * 4;
        float4 v = *reinterpret_cast<float4*>(stage + r * 64 + c4);
        __half2 h0 = __floats2half2_rn(v.x, v.y);
        __half2 h1 = __floats2half2_rn(v.z, v.w);
        uint2 o;
        o.x = *reinterpret_cast<unsigned*>(&h0);
        o.y = *reinterpret_cast<unsigned*>(&h1);
        *reinterpret_cast<uint2*>(Y + (size_t)(row0 + wm * 16 + r) * NOUT + wn * 64 + c4) = o;
    }
}

// ---------------- half2 helpers ----------------
struct H2x2 { __half2 a, b; };
__device__ __forceinline__ H2x2 ldh4(const __half* p) {
    uint2 v = *reinterpret_cast<const uint2*>(p);
    H2x2 r;
    r.a = *reinterpret_cast<__half2*>(&v.x);
    r.b = *reinterpret_cast<__half2*>(&v.y);
    return r;
}
__device__ __forceinline__ __half2 ldh2(const __half* p) {
    return *reinterpret_cast<const __half2*>(p);
}
__device__ __forceinline__ __half2 h2bits(int b) { return *reinterpret_cast<__half2*>(&b); }
__device__ __forceinline__ float atlo(int b) {
    __half2 h = *reinterpret_cast<__half2*>(&b);
    return __low2float(h);
}

// ---------------- gather 1: h[v] = dis_v*(sum y[src] + y[v]) + b  (8-wide, int4 edges) ----
template <int NOUT>
__global__ void gather1_kernel(const __half* __restrict__ y, const float* __restrict__ bias,
                               __half* __restrict__ h) {
    int warp = (blockIdx.x * blockDim.x + threadIdx.x) >> 5;
    if (warp >= NN) return;
    int lane = threadIdx.x & 31;
    int beg = g_rowptr[warp], end = g_rowptr[warp + 1];
    float d = g_dis[warp];
    if constexpr (NOUT == 128) {
        const __half* yl = y + lane * 4;
        H2x2 sv = ldh4(yl + (size_t)warp * 128);
        float2 f0 = __half22float2(sv.a), f1 = __half22float2(sv.b);
        float a0 = f0.x, a1 = f0.y, a2 = f1.x, a3 = f1.y;
        int e = beg;
        if ((e & 1) && e < end) {
            H2x2 t = ldh4(yl + (size_t)g_edge[e].x * 128);
            float2 fa = __half22float2(t.a), fb = __half22float2(t.b);
            a0 += fa.x; a1 += fa.y; a2 += fb.x; a3 += fb.y;
            e++;
        }
        for (; e + 8 <= end; e += 8) {
            int4 p0 = *reinterpret_cast<const int4*>(g_edge + e);
            int4 p1 = *reinterpret_cast<const int4*>(g_edge + e + 2);
            int4 p2 = *reinterpret_cast<const int4*>(g_edge + e + 4);
            int4 p3 = *reinterpret_cast<const int4*>(g_edge + e + 6);
            H2x2 t0 = ldh4(yl + (size_t)p0.x * 128);
            H2x2 t1 = ldh4(yl + (size_t)p0.z * 128);
            H2x2 t2 = ldh4(yl + (size_t)p1.x * 128);
            H2x2 t3 = ldh4(yl + (size_t)p1.z * 128);
            H2x2 t4 = ldh4(yl + (size_t)p2.x * 128);
            H2x2 t5 = ldh4(yl + (size_t)p2.z * 128);
            H2x2 t6 = ldh4(yl + (size_t)p3.x * 128);
            H2x2 t7 = ldh4(yl + (size_t)p3.z * 128);
            __half2 sa = __hadd2(__hadd2(__hadd2(t0.a, t1.a), __hadd2(t2.a, t3.a)),
                                 __hadd2(__hadd2(t4.a, t5.a), __hadd2(t6.a, t7.a)));
            __half2 sb = __hadd2(__hadd2(__hadd2(t0.b, t1.b), __hadd2(t2.b, t3.b)),
                                 __hadd2(__hadd2(t4.b, t5.b), __hadd2(t6.b, t7.b)));
            float2 fa = __half22float2(sa), fb = __half22float2(sb);
            a0 += fa.x; a1 += fa.y; a2 += fb.x; a3 += fb.y;
        }
        for (; e + 2 <= end; e += 2) {
            int4 p = *reinterpret_cast<const int4*>(g_edge + e);
            H2x2 t0 = ldh4(yl + (size_t)p.x * 128);
            H2x2 t1 = ldh4(yl + (size_t)p.z * 128);
            __half2 sa = __hadd2(t0.a, t1.a), sb = __hadd2(t0.b, t1.b);
            float2 fa = __half22float2(sa), fb = __half22float2(sb);
            a0 += fa.x; a1 += fa.y; a2 += fb.x; a3 += fb.y;
        }
        if (e < end) {
            H2x2 t = ldh4(yl + (size_t)g_edge[e].x * 128);
            float2 fa = __half22float2(t.a), fb = __half22float2(t.b);
            a0 += fa.x; a1 += fa.y; a2 += fb.x; a3 += fb.y;
        }
        float4 b = *reinterpret_cast<const float4*>(bias + lane * 4);
        __half2 h0 = __floats2half2_rn(a0 * d + b.x, a1 * d + b.y);
        __half2 h1 = __floats2half2_rn(a2 * d + b.z, a3 * d + b.w);
        uint2 o;
        o.x = *reinterpret_cast<unsigned*>(&h0);
        o.y = *reinterpret_cast<unsigned*>(&h1);
        *reinterpret_cast<uint2*>(h + (size_t)warp * 128 + lane * 4) = o;
    } else {
        const __half* yl = y + lane * 2;
        float2 f = __half22float2(ldh2(yl + (size_t)warp * 64));
        float a0 = f.x, a1 = f.y;
        int e = beg;
        if ((e & 1) && e < end) {
            float2 ft = __half22float2(ldh2(yl + (size_t)g_edge[e].x * 64));
            a0 += ft.x; a1 += ft.y;
            e++;
        }
        for (; e + 8 <= end; e += 8) {
            int4 p0 = *reinterpret_cast<const int4*>(g_edge + e);
            int4 p1 = *reinterpret_cast<const int4*>(g_edge + e + 2);
            int4 p2 = *reinterpret_cast<const int4*>(g_edge + e + 4);
            int4 p3 = *reinterpret_cast<const int4*>(g_edge + e + 6);
            __half2 t0 = ldh2(yl + (size_t)p0.x * 64);
            __half2 t1 = ldh2(yl + (size_t)p0.z * 64);
            __half2 t2 = ldh2(yl + (size_t)p1.x * 64);
            __half2 t3 = ldh2(yl + (size_t)p1.z * 64);
            __half2 t4 = ldh2(yl + (size_t)p2.x * 64);
            __half2 t5 = ldh2(yl + (size_t)p2.z * 64);
            __half2 t6 = ldh2(yl + (size_t)p3.x * 64);
            __half2 t7 = ldh2(yl + (size_t)p3.z * 64);
            __half2 s = __hadd2(__hadd2(__hadd2(t0, t1), __hadd2(t2, t3)),
                                __hadd2(__hadd2(t4, t5), __hadd2(t6, t7)));
            float2 fs = __half22float2(s);
            a0 += fs.x; a1 += fs.y;
        }
        for (; e + 2 <= end; e += 2) {
            int4 p = *reinterpret_cast<const int4*>(g_edge + e);
            __half2 s = __hadd2(ldh2(yl + (size_t)p.x * 64), ldh2(yl + (size_t)p.z * 64));
            float2 fs = __half22float2(s);
            a0 += fs.x; a1 += fs.y;
        }
        if (e < end) {
            float2 ft = __half22float2(ldh2(yl + (size_t)g_edge[e].x * 64));
            a0 += ft.x; a1 += ft.y;
        }
        float2 b = *reinterpret_cast<const float2*>(bias + lane * 2);
        *reinterpret_cast<__half2*>(h + (size_t)warp * 64 + lane * 2) =
            __floats2half2_rn(a0 * d + b.x, a1 * d + b.y);
    }
}

// ---------------- gather 2 + relu + LN (hidden), dis-prescaled out (8-wide, int4 edges) ----
__global__ void gather2_ln_kernel(const __half* __restrict__ h, const float* __restrict__ ew,
                                  const float* __restrict__ eb, const float* __restrict__ lg,
                                  const float* __restrict__ lb, __half* __restrict__ act) {
    int warp = (blockIdx.x * blockDim.x + threadIdx.x) >> 5;
    if (warp >= NN) return;
    int lane = threadIdx.x & 31;
    float4 ew4 = *reinterpret_cast<const float4*>(ew + lane * 4);
    float4 eb4 = *reinterpret_cast<const float4*>(eb + lane * 4);
    __half2 ewa = __floats2half2_rn(ew4.x, ew4.y), ewb = __floats2half2_rn(ew4.z, ew4.w);
    __half2 eba = __floats2half2_rn(eb4.x, eb4.y), ebb = __floats2half2_rn(eb4.z, eb4.w);
    const __half2 z2 = __floats2half2_rn(0.f, 0.f);
    int beg = g_rowptr[warp], end = g_rowptr[warp + 1];
    const __half* hl = h + lane * 4;
    float a0 = 0.f, a1 = 0.f, a2 = 0.f, a3 = 0.f;
    int e = beg;
    if ((e & 1) && e < end) {
        int2 ed = g_edge[e];
        float at = atlo(ed.y);
        H2x2 t = ldh4(hl + (size_t)ed.x * 128);
        float2 fa = __half22float2(t.a), fb = __half22float2(t.b);
        a0 += fa.x + fmaxf(at * ew4.x + eb4.x, 0.f);
        a1 += fa.y + fmaxf(at * ew4.y + eb4.y, 0.f);
        a2 += fb.x + fmaxf(at * ew4.z + eb4.z, 0.f);
        a3 += fb.y + fmaxf(at * ew4.w + eb4.w, 0.f);
        e++;
    }
    for (; e + 8 <= end; e += 8) {
        int4 p0 = *reinterpret_cast<const int4*>(g_edge + e);
        int4 p1 = *reinterpret_cast<const int4*>(g_edge + e + 2);
        int4 p2 = *reinterpret_cast<const int4*>(g_edge + e + 4);
        int4 p3 = *reinterpret_cast<const int4*>(g_edge + e + 6);
        H2x2 t0 = ldh4(hl + (size_t)p0.x * 128);
        H2x2 t1 = ldh4(hl + (size_t)p0.z * 128);
        H2x2 t2 = ldh4(hl + (size_t)p1.x * 128);
        H2x2 t3 = ldh4(hl + (size_t)p1.z * 128);
        H2x2 t4 = ldh4(hl + (size_t)p2.x * 128);
        H2x2 t5 = ldh4(hl + (size_t)p2.z * 128);
        H2x2 t6 = ldh4(hl + (size_t)p3.x * 128);
        H2x2 t7 = ldh4(hl + (size_t)p3.z * 128);
        __half2 at0 = h2bits(p0.y), at1 = h2bits(p0.w);
        __half2 at2 = h2bits(p1.y), at3 = h2bits(p1.w);
        __half2 at4 = h2bits(p2.y), at5 = h2bits(p2.w);
        __half2 at6 = h2bits(p3.y), at7 = h2bits(p3.w);
        __half2 ra = __hadd2(
            __hadd2(__hadd2(__hmax2(__hfma2(at0, ewa, eba), z2),
                            __hmax2(__hfma2(at1, ewa, eba), z2)),
                    __hadd2(__hmax2(__hfma2(at2, ewa, eba), z2),
                            __hmax2(__hfma2(at3, ewa, eba), z2))),
            __hadd2(__hadd2(__hmax2(__hfma2(at4, ewa, eba), z2),
                            __hmax2(__hfma2(at5, ewa, eba), z2)),
                    __hadd2(__hmax2(__hfma2(at6, ewa, eba), z2),
                            __hmax2(__hfma2(at7, ewa, eba), z2))));
        __half2 rb = __hadd2(
            __hadd2(__hadd2(__hmax2(__hfma2(at0, ewb, ebb), z2),
                            __hmax2(__hfma2(at1, ewb, ebb), z2)),
                    __hadd2(__hmax2(__hfma2(at2, ewb, ebb), z2),
                            __hmax2(__hfma2(at3, ewb, ebb), z2))),
            __hadd2(__hadd2(__hmax2(__hfma2(at4, ewb, ebb), z2),
                            __hmax2(__hfma2(at5, ewb, ebb), z2)),
                    __hadd2(__hmax2(__hfma2(at6, ewb, ebb), z2),
                            __hmax2(__hfma2(at7, ewb, ebb), z2))));
        __half2 sa = __hadd2(__hadd2(__hadd2(t0.a, t1.a), __hadd2(t2.a, t3.a)),
                             __hadd2(__hadd2(t4.a, t5.a), __hadd2(t6.a, t7.a)));
        __half2 sb = __hadd2(__hadd2(__hadd2(t0.b, t1.b), __hadd2(t2.b, t3.b)),
                             __hadd2(__hadd2(t4.b, t5.b), __hadd2(t6.b, t7.b)));
        float2 fa = __half22float2(__hadd2(sa, ra));
        float2 fb = __half22float2(__hadd2(sb, rb));
        a0 += fa.x; a1 += fa.y; a2 += fb.x; a3 += fb.y;
    }
    for (; e < end; e++) {
        int2 ed = g_edge[e];
        float at = atlo(ed.y);
        H2x2 t = ldh4(hl + (size_t)ed.x * 128);
        float2 fa = __half22float2(t.a), fb = __half22float2(t.b);
        a0 += fa.x + fmaxf(at * ew4.x + eb4.x, 0.f);
        a1 += fa.y + fmaxf(at * ew4.y + eb4.y, 0.f);
        a2 += fb.x + fmaxf(at * ew4.z + eb4.z, 0.f);
        a3 += fb.y + fmaxf(at * ew4.w + eb4.w, 0.f);
    }
    float inv = 1.f / fmaxf((float)(end - beg), 1.f);
    a0 = fmaxf(a0 * inv, 0.f);
    a1 = fmaxf(a1 * inv, 0.f);
    a2 = fmaxf(a2 * inv, 0.f);
    a3 = fmaxf(a3 * inv, 0.f);
    float s = a0 + a1 + a2 + a3;
    float q = a0 * a0 + a1 * a1 + a2 * a2 + a3 * a3;
#pragma unroll
    for (int off = 16; off; off >>= 1) {
        s += __shfl_xor_sync(0xffffffffu, s, off);
        q += __shfl_xor_sync(0xffffffffu, q, off);
    }
    float mu = s * (1.f / 128.f);
    float var = q * (1.f / 128.f) - mu * mu;
    float rstd = rsqrtf(var + 1e-5f);
    float4 g4 = *reinterpret_cast<const float4*>(lg + lane * 4);
    float4 b4 = *reinterpret_cast<const float4*>(lb + lane * 4);
    float d = g_dis[warp];  // pre-scale next GEMM input
    __half2 h0 = __floats2half2_rn(((a0 - mu) * rstd * g4.x + b4.x) * d,
                                   ((a1 - mu) * rstd * g4.y + b4.y) * d);
    __half2 h1 = __floats2half2_rn(((a2 - mu) * rstd * g4.z + b4.z) * d,
                                   ((a3 - mu) * rstd * g4.w + b4.w) * d);
    uint2 o;
    o.x = *reinterpret_cast<unsigned*>(&h0);
    o.y = *reinterpret_cast<unsigned*>(&h1);
    *reinterpret_cast<uint2*>(act + (size_t)warp * 128 + lane * 4) = o;
}

// ---------------- gather 2 final (NOUT=64), writes fp32 d_out (8-wide, int4 edges) ----------
__global__ void gather2_final_kernel(const __half* __restrict__ h, const float* __restrict__ ew,
                                     const float* __restrict__ eb, float* __restrict__ out) {
    int warp = (blockIdx.x * blockDim.x + threadIdx.x) >> 5;
    if (warp >= NN) return;
    int lane = threadIdx.x & 31;
    float2 ew2 = *reinterpret_cast<const float2*>(ew + lane * 2);
    float2 eb2 = *reinterpret_cast<const float2*>(eb + lane * 2);
    __half2 ewh = __floats2half2_rn(ew2.x, ew2.y);
    __half2 ebh = __floats2half2_rn(eb2.x, eb2.y);
    const __half2 z2 = __floats2half2_rn(0.f, 0.f);
    int beg = g_rowptr[warp], end = g_rowptr[warp + 1];
    const __half* hl = h + lane * 2;
    float a0 = 0.f, a1 = 0.f;
    int e = beg;
    if ((e & 1) && e < end) {
        int2 ed = g_edge[e];
        float at = atlo(ed.y);
        float2 f = __half22float2(ldh2(hl + (size_t)ed.x * 64));
        a0 += f.x + fmaxf(at * ew2.x + eb2.x, 0.f);
        a1 += f.y + fmaxf(at * ew2.y + eb2.y, 0.f);
        e++;
    }
    for (; e + 8 <= end; e += 8) {
        int4 p0 = *reinterpret_cast<const int4*>(g_edge + e);
        int4 p1 = *reinterpret_cast<const int4*>(g_edge + e + 2);
        int4 p2 = *reinterpret_cast<const int4*>(g_edge + e + 4);
        int4 p3 = *reinterpret_cast<const int4*>(g_edge + e + 6);
        __half2 t0 = ldh2(hl + (size_t)p0.x * 64);
        __half2 t1 = ldh2(hl + (size_t)p0.z * 64);
        __half2 t2 = ldh2(hl + (size_t)p1.x * 64);
        __half2 t3 = ldh2(hl + (size_t)p1.z * 64);
        __half2 t4 = ldh2(hl + (size_t)p2.x * 64);
        __half2 t5 = ldh2(hl + (size_t)p2.z * 64);
        __half2 t6 = ldh2(hl + (size_t)p3.x * 64);
        __half2 t7 = ldh2(hl + (size_t)p3.z * 64);
        __half2 at0 = h2bits(p0.y), at1 = h2bits(p0.w);
        __half2 at2 = h2bits(p1.y), at3 = h2bits(p1.w);
        __half2 at4 = h2bits(p2.y), at5 = h2bits(p2.w);
        __half2 at6 = h2bits(p3.y), at7 = h2bits(p3.w);
        __half2 r = __hadd2(
            __hadd2(__hadd2(__hmax2(__hfma2(at0, ewh, ebh), z2),
                            __hmax2(__hfma2(at1, ewh, ebh), z2)),
                    __hadd2(__hmax2(__hfma2(at2, ewh, ebh), z2),
                            __hmax2(__hfma2(at3, ewh, ebh), z2))),
            __hadd2(__hadd2(__hmax2(__hfma2(at4, ewh, ebh), z2),
                            __hmax2(__hfma2(at5, ewh, ebh), z2)),
                    __hadd2(__hmax2(__hfma2(at6, ewh, ebh), z2),
                            __hmax2(__hfma2(at7, ewh, ebh), z2))));
        __half2 sum = __hadd2(__hadd2(__hadd2(t0, t1), __hadd2(t2, t3)),
                              __hadd2(__hadd2(t4, t5), __hadd2(t6, t7)));
        float2 f = __half22float2(__hadd2(sum, r));
        a0 += f.x; a1 += f.y;
    }
    for (; e < end; e++) {
        int2 ed = g_edge[e];
        float at = atlo(ed.y);
        float2 f = __half22float2(ldh2(hl + (size_t)ed.x * 64));
        a0 += f.x + fmaxf(at * ew2.x + eb2.x, 0.f);
        a1 += f.y + fmaxf(at * ew2.y + eb2.y, 0.f);
    }
    float inv = 1.f / fmaxf((float)(end - beg), 1.f);
    *reinterpret_cast<float2*>(out + (size_t)warp * 64 + lane * 2) =
        make_float2(a0 * inv, a1 * inv);
}

// ---------------- global mean pool ----------------
__global__ void pool_kernel(float* __restrict__ out) {
    __shared__ float sred[256];
    __shared__ int s_start, s_cnt;
    int g = blockIdx.x, t = threadIdx.x;
    if (t == 0) {
        int st = 0;
        for (int j = 0; j < g; j++) st += g_cnt[NN + j];
        s_start = st;
        s_cnt = g_cnt[NN + g];
    }
    __syncthreads();
    int start = s_start, cnt = s_cnt;
    int f = t & 63, sub = t >> 6;
    float p = 0.f;
    for (int i = start + sub; i < start + cnt; i += 4) p += out[(size_t)i * 64 + f];
    sred[t] = p;
    __syncthreads();
    if (t < 64) {
        float s = sred[t] + sred[t + 64] + sred[t + 128] + sred[t + 192];
        out[(size_t)NN * 64 + g * 64 + f] = s / fmaxf((float)cnt, 1.0f);
    }
}

// ---------------- launch ----------------
extern "C" void kernel_launch(void* const* d_in, const int* in_sizes, int n_in,
                              void* d_out, int out_size) {
    const float* x = (const float*)d_in[0];
    const int* ei = (const int*)d_in[1];
    const float* ea = (const float*)d_in[2];
    const int* batch = (const int*)d_in[3];
    const float* gw0 = (const float*)d_in[4];
    const float* gb0 = (const float*)d_in[5];
    const float* ew0 = (const float*)d_in[6];
    const float* eb0 = (const float*)d_in[7];
    const float* lg0 = (const float*)d_in[8];
    const float* lb0 = (const float*)d_in[9];
    const float* gw1 = (const float*)d_in[10];
    const float* gb1 = (const float*)d_in[11];
    const float* ew1 = (const float*)d_in[12];
    const float* eb1 = (const float*)d_in[13];
    const float* lg1 = (const float*)d_in[14];
    const float* lb1 = (const float*)d_in[15];
    const float* gw2 = (const float*)d_in[16];
    const float* gb2 = (const float*)d_in[17];
    const float* ew2 = (const float*)d_in[18];
    const float* eb2 = (const float*)d_in[19];
    float* out = (float*)d_out;

    __half *xh, *w0h, *w1h, *w2h, *yp, *hp, *ap;
    void* cntp;
    cudaGetSymbolAddress(&cntp, g_cnt);
    cudaGetSymbolAddress((void**)&xh, g_xh);
    cudaGetSymbolAddress((void**)&w0h, g_w0h);
    cudaGetSymbolAddress((void**)&w1h, g_w1h);
    cudaGetSymbolAddress((void**)&w2h, g_w2h);
    cudaGetSymbolAddress((void**)&yp, g_y);
    cudaGetSymbolAddress((void**)&hp, g_h);
    cudaGetSymbolAddress((void**)&ap, g_act);

    const int WARP_GRID = (NN * 32 + 255) / 256;

    cudaMemsetAsync(cntp, 0, (NN + GG) * sizeof(int));

    count_kernel<<<(EE + 255) / 256, 256>>>(ei, batch);
    scan_kernel<<<1, 1024>>>();
    fill_kernel<<<(EE + 255) / 256, 256>>>(ei, ea);
    convert_kernel<<<NB_CONVX + NB_CONVW, 256>>>(x, gw0, gw1, gw2);

    // layer 0
    hgemm_kernel<128, 64><<<PADN / 64, 256>>>(xh, w0h, yp);
    gather1_kernel<128><<<WARP_GRID, 256>>>(yp, gb0, hp);
    gather2_ln_kernel<<<WARP_GRID, 256>>>(hp, ew0, eb0, lg0, lb0, ap);

    // layer 1
    hgemm_kernel<128, 64><<<PADN / 64, 256>>>(ap, w1h, yp);
    gather1_kernel<128><<<WARP_GRID, 256>>>(yp, gb1, hp);
    gather2_ln_kernel<<<WARP_GRID, 256>>>(hp, ew1, eb1, lg1, lb1, ap);

    // layer 2
    hgemm_kernel<64, 128><<<PADN / 128, 256>>>(ap, w2h, yp);
    gather1_kernel<64><<<WARP_GRID, 256>>>(yp, gb2, hp);
    gather2_final_kernel<<<WARP_GRID, 256>>>(hp, ew2, eb2, out);

    pool_kernel<<<GG, 256>>>(out);
}

// round 17
// speedup vs baseline: 1.1392x; 1.0250x over previous
#include <cuda_runtime.h>
#include <cuda_fp16.h>
#include <mma.h>
#include <math.h>
using namespace nvcuda;

#define NN 50000
#define PADN 50048
#define EE 800000
#define GG 64

// ---------------- device scratch ----------------
__device__ int    g_cnt[NN];
__device__ int    g_rowptr[NN + 1];
__device__ int    g_eoff[EE];        // per-edge within-node offset (from count's atomic)
__device__ __align__(16) int2 g_edge[EE];  // {src, bits(eattr)}
__device__ float  g_dis[NN];
__device__ int    g_gcnt[GG];
__device__ __half g_xh[PADN * 128];  // dis-scaled fp16 layer-0 input
__device__ __half g_w0h[128 * 128];
__device__ __half g_w1h[128 * 128];
__device__ __half g_w2h[128 * 64];
__device__ __half g_y[PADN * 128];   // GEMM out: dis ⊙ (in @ W)
__device__ __half g_h[PADN * 128];   // gcn out
__device__ __half g_act[PADN * 128]; // dis-scaled activation

// ---------------- count (returns per-edge slot via atomic) ----------------
__global__ void count_kernel(const int* __restrict__ ei, const int* __restrict__ batch) {
    int i = blockIdx.x * blockDim.x + threadIdx.x;
    if (i < EE) g_eoff[i] = atomicAdd(&g_cnt[ei[EE + i]], 1);
    if (i < NN) atomicAdd(&g_gcnt[batch[i]], 1);
}

// ---------------- single-block scan (+dis), COALESCED looped form ----------------
__global__ void scan_kernel() {
    __shared__ int wsum[32];
    __shared__ int s_carry, s_tot;
    int tid = threadIdx.x, lane = tid & 31, wid = tid >> 5;
    if (tid == 0) s_carry = 0;
    __syncthreads();
    for (int base = 0; base < NN; base += 1024) {
        int i = base + tid;
        int v = (i < NN) ? g_cnt[i] : 0;
        int val = v;
#pragma unroll
        for (int off = 1; off < 32; off <<= 1) {
            int t = __shfl_up_sync(0xffffffffu, val, off);
            if (lane >= off) val += t;
        }
        if (lane == 31) wsum[wid] = val;
        __syncthreads();
        if (wid == 0) {
            int wv = wsum[lane];
            int wi = wv;
#pragma unroll
            for (int off = 1; off < 32; off <<= 1) {
                int t = __shfl_up_sync(0xffffffffu, wi, off);
                if (lane >= off) wi += t;
            }
            wsum[lane] = wi - wv;
            if (lane == 31) s_tot = wi;
        }
        __syncthreads();
        int carry = s_carry;
        if (i < NN) {
            int excl = carry + wsum[wid] + (val - v);
            g_rowptr[i] = excl;
            g_dis[i] = rsqrtf((float)v + 1.0f);
        }
        __syncthreads();
        if (tid == 0) s_carry = carry + s_tot;
        __syncthreads();
    }
    if (threadIdx.x == 0) g_rowptr[NN] = s_carry;
}

// ---------------- fill (atomic-free: rowptr + precomputed offset) ----------------
__global__ void fill_kernel(const int* __restrict__ ei, const float* __restrict__ ea) {
    int i = blockIdx.x * blockDim.x + threadIdx.x;
    if (i < EE) {
        int d = ei[EE + i];
        int p = g_rowptr[d] + g_eoff[i];
        g_edge[p] = make_int2(ei[i], __float_as_int(ea[i]));
    }
}

// ---------------- fused conversion: x (dis-scaled) || weights ----------------
#define NB_CONVX 3128  // PADN*128 / (256*8)
#define NB_CONVW 80    // 20480 float2 / 256
__global__ void convert_kernel(const float* __restrict__ x, const float* __restrict__ w0,
                               const float* __restrict__ w1, const float* __restrict__ w2) {
    int b = blockIdx.x, tid = threadIdx.x;
    if (b < NB_CONVX) {
        int base = (b * 256 + tid) * 8;
        int row = base >> 7;
        int4 o;
        if (row < NN) {
            float d = g_dis[row];
            float4 v0 = *reinterpret_cast<const float4*>(x + base);
            float4 v1 = *reinterpret_cast<const float4*>(x + base + 4);
            __half2 h0 = __floats2half2_rn(v0.x * d, v0.y * d);
            __half2 h1 = __floats2half2_rn(v0.z * d, v0.w * d);
            __half2 h2 = __floats2half2_rn(v1.x * d, v1.y * d);
            __half2 h3 = __floats2half2_rn(v1.z * d, v1.w * d);
            o.x = *reinterpret_cast<int*>(&h0);
            o.y = *reinterpret_cast<int*>(&h1);
            o.z = *reinterpret_cast<int*>(&h2);
            o.w = *reinterpret_cast<int*>(&h3);
        } else {
            o = make_int4(0, 0, 0, 0);
        }
        *reinterpret_cast<int4*>(g_xh + base) = o;
    } else {
        int i = (b - NB_CONVX) * 256 + tid;  // float2 units
        const float* src;
        __half* dst;
        int off;
        if (i < 8192) { src = w0; dst = g_w0h; off = i; }
        else if (i < 16384) { src = w1; dst = g_w1h; off = i - 8192; }
        else { src = w2; dst = g_w2h; off = i - 16384; }
        float2 v = *reinterpret_cast<const float2*>(src + off * 2);
        *reinterpret_cast<__half2*>(dst + off * 2) = __floats2half2_rn(v.x, v.y);
    }
}

// ---------------- HMMA GEMM ----------------
template <int NOUT, int BM>
__global__ void hgemm_kernel(const __half* __restrict__ A, const __half* __restrict__ Bw,
                             __half* __restrict__ Y) {
    constexpr int KC = 64;
    constexpr int WARPS_M = BM / 16;
    constexpr int LDA = KC + 8;
    constexpr int LDB = NOUT + 8;
    constexpr int A_BYTES = BM * LDA * 2;
    constexpr int B_BYTES = KC * LDB * 2;
    constexpr int SMEM_BYTES = (A_BYTES + B_BYTES) > 32768 ? (A_BYTES + B_BYTES) : 32768;
    __shared__ __align__(16) char smem_raw[SMEM_BYTES];
    __half* sA = reinterpret_cast<__half*>(smem_raw);
    __half* sB = reinterpret_cast<__half*>(smem_raw + A_BYTES);

    int tid = threadIdx.x;
    int warp = tid >> 5, lane = tid & 31;
    int wm = warp % WARPS_M, wn = warp / WARPS_M;
    int row0 = blockIdx.x * BM;

    wmma::fragment<wmma::accumulator, 16, 16, 16, float> acc[4];
#pragma unroll
    for (int f = 0; f < 4; f++) wmma::fill_fragment(acc[f], 0.f);

    for (int kc = 0; kc < 2; kc++) {
        for (int idx = tid; idx < BM * KC / 8; idx += 256) {
            int r = idx / (KC / 8), cg = idx % (KC / 8);
            *reinterpret_cast<int4*>(sA + r * LDA + cg * 8) =
                *reinterpret_cast<const int4*>(A + (size_t)(row0 + r) * 128 + kc * KC + cg * 8);
        }
        for (int idx = tid; idx < KC * NOUT / 8; idx += 256) {
            int r = idx / (NOUT / 8), cg = idx % (NOUT / 8);
            *reinterpret_cast<int4*>(sB + r * LDB + cg * 8) =
                *reinterpret_cast<const int4*>(Bw + (size_t)(kc * KC + r) * NOUT + cg * 8);
        }
        __syncthreads();
#pragma unroll
        for (int k16 = 0; k16 < 4; k16++) {
            wmma::fragment<wmma::matrix_a, 16, 16, 16, __half, wmma::row_major> af;
            wmma::load_matrix_sync(af, sA + (wm * 16) * LDA + k16 * 16, LDA);
#pragma unroll
            for (int f = 0; f < 4; f++) {
                wmma::fragment<wmma::matrix_b, 16, 16, 16, __half, wmma::row_major> bf;
                wmma::load_matrix_sync(bf, sB + (k16 * 16) * LDB + wn * 64 + f * 16, LDB);
                wmma::mma_sync(acc[f], af, bf, acc[f]);
            }
        }
        __syncthreads();
    }
    float* stage = reinterpret_cast<float*>(smem_raw) + warp * 16 * 64;
#pragma unroll
    for (int f = 0; f < 4; f++)
        wmma::store_matrix_sync(stage + f * 16, acc[f], 64, wmma::mem_row_major);
    __syncwarp();
    for (int idx = lane; idx < 256; idx += 32) {
        int r = idx >> 4, c4 = (idx & 15) * 4;
        float4 v = *reinterpret_cast<float4*>(stage + r * 64 + c4);
        __half2 h0 = __floats2half2_rn(v.x, v.y);
        __half2 h1 = __floats2half2_rn(v.z, v.w);
        uint2 o;
        o.x = *reinterpret_cast<unsigned*>(&h0);
        o.y = *reinterpret_cast<unsigned*>(&h1);
        *reinterpret_cast<uint2*>(Y + (size_t)(row0 + wm * 16 + r) * NOUT + wn * 64 + c4) = o;
    }
}

// ---------------- half2 helpers ----------------
struct H2x2 { __half2 a, b; };
__device__ __forceinline__ H2x2 ldh4(const __half* p) {
    uint2 v = *reinterpret_cast<const uint2*>(p);
    H2x2 r;
    r.a = *reinterpret_cast<__half2*>(&v.x);
    r.b = *reinterpret_cast<__half2*>(&v.y);
    return r;
}
__device__ __forceinline__ __half2 ldh2(const __half* p) {
    return *reinterpret_cast<const __half2*>(p);
}

// ---------------- gather 1: h[v] = dis_v*(sum y[src] + y[v]) + b  (8-wide, int4 edges) ----
template <int NOUT>
__global__ void gather1_kernel(const __half* __restrict__ y, const float* __restrict__ bias,
                               __half* __restrict__ h) {
    int warp = (blockIdx.x * blockDim.x + threadIdx.x) >> 5;
    if (warp >= NN) return;
    int lane = threadIdx.x & 31;
    int beg = g_rowptr[warp], end = g_rowptr[warp + 1];
    float d = g_dis[warp];
    if constexpr (NOUT == 128) {
        const __half* yl = y + lane * 4;
        H2x2 sv = ldh4(yl + (size_t)warp * 128);
        float2 f0 = __half22float2(sv.a), f1 = __half22float2(sv.b);
        float a0 = f0.x, a1 = f0.y, a2 = f1.x, a3 = f1.y;
        int e = beg;
        if ((e & 1) && e < end) {
            H2x2 t = ldh4(yl + (size_t)g_edge[e].x * 128);
            float2 fa = __half22float2(t.a), fb = __half22float2(t.b);
            a0 += fa.x; a1 += fa.y; a2 += fb.x; a3 += fb.y;
            e++;
        }
        for (; e + 8 <= end; e += 8) {
            int4 p0 = *reinterpret_cast<const int4*>(g_edge + e);
            int4 p1 = *reinterpret_cast<const int4*>(g_edge + e + 2);
            int4 p2 = *reinterpret_cast<const int4*>(g_edge + e + 4);
            int4 p3 = *reinterpret_cast<const int4*>(g_edge + e + 6);
            H2x2 t0 = ldh4(yl + (size_t)p0.x * 128);
            H2x2 t1 = ldh4(yl + (size_t)p0.z * 128);
            H2x2 t2 = ldh4(yl + (size_t)p1.x * 128);
            H2x2 t3 = ldh4(yl + (size_t)p1.z * 128);
            H2x2 t4 = ldh4(yl + (size_t)p2.x * 128);
            H2x2 t5 = ldh4(yl + (size_t)p2.z * 128);
            H2x2 t6 = ldh4(yl + (size_t)p3.x * 128);
            H2x2 t7 = ldh4(yl + (size_t)p3.z * 128);
            __half2 sa = __hadd2(__hadd2(__hadd2(t0.a, t1.a), __hadd2(t2.a, t3.a)),
                                 __hadd2(__hadd2(t4.a, t5.a), __hadd2(t6.a, t7.a)));
            __half2 sb = __hadd2(__hadd2(__hadd2(t0.b, t1.b), __hadd2(t2.b, t3.b)),
                                 __hadd2(__hadd2(t4.b, t5.b), __hadd2(t6.b, t7.b)));
            float2 fa = __half22float2(sa), fb = __half22float2(sb);
            a0 += fa.x; a1 += fa.y; a2 += fb.x; a3 += fb.y;
        }
        for (; e + 2 <= end; e += 2) {
            int4 p = *reinterpret_cast<const int4*>(g_edge + e);
            H2x2 t0 = ldh4(yl + (size_t)p.x * 128);
            H2x2 t1 = ldh4(yl + (size_t)p.z * 128);
            __half2 sa = __hadd2(t0.a, t1.a), sb = __hadd2(t0.b, t1.b);
            float2 fa = __half22float2(sa), fb = __half22float2(sb);
            a0 += fa.x; a1 += fa.y; a2 += fb.x; a3 += fb.y;
        }
        if (e < end) {
            H2x2 t = ldh4(yl + (size_t)g_edge[e].x * 128);
            float2 fa = __half22float2(t.a), fb = __half22float2(t.b);
            a0 += fa.x; a1 += fa.y; a2 += fb.x; a3 += fb.y;
        }
        float4 b = *reinterpret_cast<const float4*>(bias + lane * 4);
        __half2 h0 = __floats2half2_rn(a0 * d + b.x, a1 * d + b.y);
        __half2 h1 = __floats2half2_rn(a2 * d + b.z, a3 * d + b.w);
        uint2 o;
        o.x = *reinterpret_cast<unsigned*>(&h0);
        o.y = *reinterpret_cast<unsigned*>(&h1);
        *reinterpret_cast<uint2*>(h + (size_t)warp * 128 + lane * 4) = o;
    } else {
        const __half* yl = y + lane * 2;
        float2 f = __half22float2(ldh2(yl + (size_t)warp * 64));
        float a0 = f.x, a1 = f.y;
        int e = beg;
        if ((e & 1) && e < end) {
            float2 ft = __half22float2(ldh2(yl + (size_t)g_edge[e].x * 64));
            a0 += ft.x; a1 += ft.y;
            e++;
        }
        for (; e + 8 <= end; e += 8) {
            int4 p0 = *reinterpret_cast<const int4*>(g_edge + e);
            int4 p1 = *reinterpret_cast<const int4*>(g_edge + e + 2);
            int4 p2 = *reinterpret_cast<const int4*>(g_edge + e + 4);
            int4 p3 = *reinterpret_cast<const int4*>(g_edge + e + 6);
            __half2 t0 = ldh2(yl + (size_t)p0.x * 64);
            __half2 t1 = ldh2(yl + (size_t)p0.z * 64);
            __half2 t2 = ldh2(yl + (size_t)p1.x * 64);
            __half2 t3 = ldh2(yl + (size_t)p1.z * 64);
            __half2 t4 = ldh2(yl + (size_t)p2.x * 64);
            __half2 t5 = ldh2(yl + (size_t)p2.z * 64);
            __half2 t6 = ldh2(yl + (size_t)p3.x * 64);
            __half2 t7 = ldh2(yl + (size_t)p3.z * 64);
            __half2 s = __hadd2(__hadd2(__hadd2(t0, t1), __hadd2(t2, t3)),
                                __hadd2(__hadd2(t4, t5), __hadd2(t6, t7)));
            float2 fs = __half22float2(s);
            a0 += fs.x; a1 += fs.y;
        }
        for (; e + 2 <= end; e += 2) {
            int4 p = *reinterpret_cast<const int4*>(g_edge + e);
            __half2 s = __hadd2(ldh2(yl + (size_t)p.x * 64), ldh2(yl + (size_t)p.z * 64));
            float2 fs = __half22float2(s);
            a0 += fs.x; a1 += fs.y;
        }
        if (e < end) {
            float2 ft = __half22float2(ldh2(yl + (size_t)g_edge[e].x * 64));
            a0 += ft.x; a1 += ft.y;
        }
        float2 b = *reinterpret_cast<const float2*>(bias + lane * 2);
        *reinterpret_cast<__half2*>(h + (size_t)warp * 64 + lane * 2) =
            __floats2half2_rn(a0 * d + b.x, a1 * d + b.y);
    }
}

// ---------------- gather 2 + relu + LN (hidden), dis-prescaled out (8-wide, int4 edges) ----
__global__ void gather2_ln_kernel(const __half* __restrict__ h, const float* __restrict__ ew,
                                  const float* __restrict__ eb, const float* __restrict__ lg,
                                  const float* __restrict__ lb, __half* __restrict__ act) {
    int warp = (blockIdx.x * blockDim.x + threadIdx.x) >> 5;
    if (warp >= NN) return;
    int lane = threadIdx.x & 31;
    float4 ew4 = *reinterpret_cast<const float4*>(ew + lane * 4);
    float4 eb4 = *reinterpret_cast<const float4*>(eb + lane * 4);
    __half2 ewa = __floats2half2_rn(ew4.x, ew4.y), ewb = __floats2half2_rn(ew4.z, ew4.w);
    __half2 eba = __floats2half2_rn(eb4.x, eb4.y), ebb = __floats2half2_rn(eb4.z, eb4.w);
    const __half2 z2 = __floats2half2_rn(0.f, 0.f);
    int beg = g_rowptr[warp], end = g_rowptr[warp + 1];
    const __half* hl = h + lane * 4;
    float a0 = 0.f, a1 = 0.f, a2 = 0.f, a3 = 0.f;
    int e = beg;
    if ((e & 1) && e < end) {
        int2 ed = g_edge[e];
        float at = __int_as_float(ed.y);
        H2x2 t = ldh4(hl + (size_t)ed.x * 128);
        float2 fa = __half22float2(t.a), fb = __half22float2(t.b);
        a0 += fa.x + fmaxf(at * ew4.x + eb4.x, 0.f);
        a1 += fa.y + fmaxf(at * ew4.y + eb4.y, 0.f);
        a2 += fb.x + fmaxf(at * ew4.z + eb4.z, 0.f);
        a3 += fb.y + fmaxf(at * ew4.w + eb4.w, 0.f);
        e++;
    }
    for (; e + 8 <= end; e += 8) {
        int4 p0 = *reinterpret_cast<const int4*>(g_edge + e);
        int4 p1 = *reinterpret_cast<const int4*>(g_edge + e + 2);
        int4 p2 = *reinterpret_cast<const int4*>(g_edge + e + 4);
        int4 p3 = *reinterpret_cast<const int4*>(g_edge + e + 6);
        H2x2 t0 = ldh4(hl + (size_t)p0.x * 128);
        H2x2 t1 = ldh4(hl + (size_t)p0.z * 128);
        H2x2 t2 = ldh4(hl + (size_t)p1.x * 128);
        H2x2 t3 = ldh4(hl + (size_t)p1.z * 128);
        H2x2 t4 = ldh4(hl + (size_t)p2.x * 128);
        H2x2 t5 = ldh4(hl + (size_t)p2.z * 128);
        H2x2 t6 = ldh4(hl + (size_t)p3.x * 128);
        H2x2 t7 = ldh4(hl + (size_t)p3.z * 128);
        __half2 at0 = __float2half2_rn(__int_as_float(p0.y));
        __half2 at1 = __float2half2_rn(__int_as_float(p0.w));
        __half2 at2 = __float2half2_rn(__int_as_float(p1.y));
        __half2 at3 = __float2half2_rn(__int_as_float(p1.w));
        __half2 at4 = __float2half2_rn(__int_as_float(p2.y));
        __half2 at5 = __float2half2_rn(__int_as_float(p2.w));
        __half2 at6 = __float2half2_rn(__int_as_float(p3.y));
        __half2 at7 = __float2half2_rn(__int_as_float(p3.w));
        __half2 ra = __hadd2(
            __hadd2(__hadd2(__hmax2(__hfma2(at0, ewa, eba), z2),
                            __hmax2(__hfma2(at1, ewa, eba), z2)),
                    __hadd2(__hmax2(__hfma2(at2, ewa, eba), z2),
                            __hmax2(__hfma2(at3, ewa, eba), z2))),
            __hadd2(__hadd2(__hmax2(__hfma2(at4, ewa, eba), z2),
                            __hmax2(__hfma2(at5, ewa, eba), z2)),
                    __hadd2(__hmax2(__hfma2(at6, ewa, eba), z2),
                            __hmax2(__hfma2(at7, ewa, eba), z2))));
        __half2 rb = __hadd2(
            __hadd2(__hadd2(__hmax2(__hfma2(at0, ewb, ebb), z2),
                            __hmax2(__hfma2(at1, ewb, ebb), z2)),
                    __hadd2(__hmax2(__hfma2(at2, ewb, ebb), z2),
                            __hmax2(__hfma2(at3, ewb, ebb), z2))),
            __hadd2(__hadd2(__hmax2(__hfma2(at4, ewb, ebb), z2),
                            __hmax2(__hfma2(at5, ewb, ebb), z2)),
                    __hadd2(__hmax2(__hfma2(at6, ewb, ebb), z2),
                            __hmax2(__hfma2(at7, ewb, ebb), z2))));
        __half2 sa = __hadd2(__hadd2(__hadd2(t0.a, t1.a), __hadd2(t2.a, t3.a)),
                             __hadd2(__hadd2(t4.a, t5.a), __hadd2(t6.a, t7.a)));
        __half2 sb = __hadd2(__hadd2(__hadd2(t0.b, t1.b), __hadd2(t2.b, t3.b)),
                             __hadd2(__hadd2(t4.b, t5.b), __hadd2(t6.b, t7.b)));
        float2 fa = __half22float2(__hadd2(sa, ra));
        float2 fb = __half22float2(__hadd2(sb, rb));
        a0 += fa.x; a1 += fa.y; a2 += fb.x; a3 += fb.y;
    }
    for (; e < end; e++) {
        int2 ed = g_edge[e];
        float at = __int_as_float(ed.y);
        H2x2 t = ldh4(hl + (size_t)ed.x * 128);
        float2 fa = __half22float2(t.a), fb = __half22float2(t.b);
        a0 += fa.x + fmaxf(at * ew4.x + eb4.x, 0.f);
        a1 += fa.y + fmaxf(at * ew4.y + eb4.y, 0.f);
        a2 += fb.x + fmaxf(at * ew4.z + eb4.z, 0.f);
        a3 += fb.y + fmaxf(at * ew4.w + eb4.w, 0.f);
    }
    float inv = 1.f / fmaxf((float)(end - beg), 1.f);
    a0 = fmaxf(a0 * inv, 0.f);
    a1 = fmaxf(a1 * inv, 0.f);
    a2 = fmaxf(a2 * inv, 0.f);
    a3 = fmaxf(a3 * inv, 0.f);
    float s = a0 + a1 + a2 + a3;
    float q = a0 * a0 + a1 * a1 + a2 * a2 + a3 * a3;
#pragma unroll
    for (int off = 16; off; off >>= 1) {
        s += __shfl_xor_sync(0xffffffffu, s, off);
        q += __shfl_xor_sync(0xffffffffu, q, off);
    }
    float mu = s * (1.f / 128.f);
    float var = q * (1.f / 128.f) - mu * mu;
    float rstd = rsqrtf(var + 1e-5f);
    float4 g4 = *reinterpret_cast<const float4*>(lg + lane * 4);
    float4 b4 = *reinterpret_cast<const float4*>(lb + lane * 4);
    float d = g_dis[warp];  // pre-scale next GEMM input
    __half2 h0 = __floats2half2_rn(((a0 - mu) * rstd * g4.x + b4.x) * d,
                                   ((a1 - mu) * rstd * g4.y + b4.y) * d);
    __half2 h1 = __floats2half2_rn(((a2 - mu) * rstd * g4.z + b4.z) * d,
                                   ((a3 - mu) * rstd * g4.w + b4.w) * d);
    uint2 o;
    o.x = *reinterpret_cast<unsigned*>(&h0);
    o.y = *reinterpret_cast<unsigned*>(&h1);
    *reinterpret_cast<uint2*>(act + (size_t)warp * 128 + lane * 4) = o;
}

// ---------------- gather 2 final (NOUT=64), writes fp32 d_out (8-wide, int4 edges) ----------
__global__ void gather2_final_kernel(const __half* __restrict__ h, const float* __restrict__ ew,
                                     const float* __restrict__ eb, float* __restrict__ out) {
    int warp = (blockIdx.x * blockDim.x + threadIdx.x) >> 5;
    if (warp >= NN) return;
    int lane = threadIdx.x & 31;
    float2 ew2 = *reinterpret_cast<const float2*>(ew + lane * 2);
    float2 eb2 = *reinterpret_cast<const float2*>(eb + lane * 2);
    __half2 ewh = __floats2half2_rn(ew2.x, ew2.y);
    __half2 ebh = __floats2half2_rn(eb2.x, eb2.y);
    const __half2 z2 = __floats2half2_rn(0.f, 0.f);
    int beg = g_rowptr[warp], end = g_rowptr[warp + 1];
    const __half* hl = h + lane * 2;
    float a0 = 0.f, a1 = 0.f;
    int e = beg;
    if ((e & 1) && e < end) {
        int2 ed = g_edge[e];
        float at = __int_as_float(ed.y);
        float2 f = __half22float2(ldh2(hl + (size_t)ed.x * 64));
        a0 += f.x + fmaxf(at * ew2.x + eb2.x, 0.f);
        a1 += f.y + fmaxf(at * ew2.y + eb2.y, 0.f);
        e++;
    }
    for (; e + 8 <= end; e += 8) {
        int4 p0 = *reinterpret_cast<const int4*>(g_edge + e);
        int4 p1 = *reinterpret_cast<const int4*>(g_edge + e + 2);
        int4 p2 = *reinterpret_cast<const int4*>(g_edge + e + 4);
        int4 p3 = *reinterpret_cast<const int4*>(g_edge + e + 6);
        __half2 t0 = ldh2(hl + (size_t)p0.x * 64);
        __half2 t1 = ldh2(hl + (size_t)p0.z * 64);
        __half2 t2 = ldh2(hl + (size_t)p1.x * 64);
        __half2 t3 = ldh2(hl + (size_t)p1.z * 64);
        __half2 t4 = ldh2(hl + (size_t)p2.x * 64);
        __half2 t5 = ldh2(hl + (size_t)p2.z * 64);
        __half2 t6 = ldh2(hl + (size_t)p3.x * 64);
        __half2 t7 = ldh2(hl + (size_t)p3.z * 64);
        __half2 at0 = __float2half2_rn(__int_as_float(p0.y));
        __half2 at1 = __float2half2_rn(__int_as_float(p0.w));
        __half2 at2 = __float2half2_rn(__int_as_float(p1.y));
        __half2 at3 = __float2half2_rn(__int_as_float(p1.w));
        __half2 at4 = __float2half2_rn(__int_as_float(p2.y));
        __half2 at5 = __float2half2_rn(__int_as_float(p2.w));
        __half2 at6 = __float2half2_rn(__int_as_float(p3.y));
        __half2 at7 = __float2half2_rn(__int_as_float(p3.w));
        __half2 r = __hadd2(
            __hadd2(__hadd2(__hmax2(__hfma2(at0, ewh, ebh), z2),
                            __hmax2(__hfma2(at1, ewh, ebh), z2)),
                    __hadd2(__hmax2(__hfma2(at2, ewh, ebh), z2),
                            __hmax2(__hfma2(at3, ewh, ebh), z2))),
            __hadd2(__hadd2(__hmax2(__hfma2(at4, ewh, ebh), z2),
                            __hmax2(__hfma2(at5, ewh, ebh), z2)),
                    __hadd2(__hmax2(__hfma2(at6, ewh, ebh), z2),
                            __hmax2(__hfma2(at7, ewh, ebh), z2))));
        __half2 sum = __hadd2(__hadd2(__hadd2(t0, t1), __hadd2(t2, t3)),
                              __hadd2(__hadd2(t4, t5), __hadd2(t6, t7)));
        float2 f = __half22float2(__hadd2(sum, r));
        a0 += f.x; a1 += f.y;
    }
    for (; e < end; e++) {
        int2 ed = g_edge[e];
        float at = __int_as_float(ed.y);
        float2 f = __half22float2(ldh2(hl + (size_t)ed.x * 64));
        a0 += f.x + fmaxf(at * ew2.x + eb2.x, 0.f);
        a1 += f.y + fmaxf(at * ew2.y + eb2.y, 0.f);
    }
    float inv = 1.f / fmaxf((float)(end - beg), 1.f);
    *reinterpret_cast<float2*>(out + (size_t)warp * 64 + lane * 2) =
        make_float2(a0 * inv, a1 * inv);
}

// ---------------- global mean pool ----------------
__global__ void pool_kernel(float* __restrict__ out) {
    __shared__ float sred[256];
    __shared__ int s_start, s_cnt;
    int g = blockIdx.x, t = threadIdx.x;
    if (t == 0) {
        int st = 0;
        for (int j = 0; j < g; j++) st += g_gcnt[j];
        s_start = st;
        s_cnt = g_gcnt[g];
    }
    __syncthreads();
    int start = s_start, cnt = s_cnt;
    int f = t & 63, sub = t >> 6;
    float p = 0.f;
    for (int i = start + sub; i < start + cnt; i += 4) p += out[(size_t)i * 64 + f];
    sred[t] = p;
    __syncthreads();
    if (t < 64) {
        float s = sred[t] + sred[t + 64] + sred[t + 128] + sred[t + 192];
        out[(size_t)NN * 64 + g * 64 + f] = s / fmaxf((float)cnt, 1.0f);
    }
}

// ---------------- launch ----------------
extern "C" void kernel_launch(void* const* d_in, const int* in_sizes, int n_in,
                              void* d_out, int out_size) {
    const float* x = (const float*)d_in[0];
    const int* ei = (const int*)d_in[1];
    const float* ea = (const float*)d_in[2];
    const int* batch = (const int*)d_in[3];
    const float* gw0 = (const float*)d_in[4];
    const float* gb0 = (const float*)d_in[5];
    const float* ew0 = (const float*)d_in[6];
    const float* eb0 = (const float*)d_in[7];
    const float* lg0 = (const float*)d_in[8];
    const float* lb0 = (const float*)d_in[9];
    const float* gw1 = (const float*)d_in[10];
    const float* gb1 = (const float*)d_in[11];
    const float* ew1 = (const float*)d_in[12];
    const float* eb1 = (const float*)d_in[13];
    const float* lg1 = (const float*)d_in[14];
    const float* lb1 = (const float*)d_in[15];
    const float* gw2 = (const float*)d_in[16];
    const float* gb2 = (const float*)d_in[17];
    const float* ew2 = (const float*)d_in[18];
    const float* eb2 = (const float*)d_in[19];
    float* out = (float*)d_out;

    __half *xh, *w0h, *w1h, *w2h, *yp, *hp, *ap;
    void *cntp, *gcntp;
    cudaGetSymbolAddress(&cntp, g_cnt);
    cudaGetSymbolAddress(&gcntp, g_gcnt);
    cudaGetSymbolAddress((void**)&xh, g_xh);
    cudaGetSymbolAddress((void**)&w0h, g_w0h);
    cudaGetSymbolAddress((void**)&w1h, g_w1h);
    cudaGetSymbolAddress((void**)&w2h, g_w2h);
    cudaGetSymbolAddress((void**)&yp, g_y);
    cudaGetSymbolAddress((void**)&hp, g_h);
    cudaGetSymbolAddress((void**)&ap, g_act);

    const int WARP_GRID = (NN * 32 + 255) / 256;

    cudaMemsetAsync(cntp, 0, NN * sizeof(int));
    cudaMemsetAsync(gcntp, 0, GG * sizeof(int));

    count_kernel<<<(EE + 255) / 256, 256>>>(ei, batch);
    scan_kernel<<<1, 1024>>>();
    fill_kernel<<<(EE + 255) / 256, 256>>>(ei, ea);
    convert_kernel<<<NB_CONVX + NB_CONVW, 256>>>(x, gw0, gw1, gw2);

    // layer 0
    hgemm_kernel<128, 64><<<PADN / 64, 256>>>(xh, w0h, yp);
    gather1_kernel<128><<<WARP_GRID, 256>>>(yp, gb0, hp);
    gather2_ln_kernel<<<WARP_GRID, 256>>>(hp, ew0, eb0, lg0, lb0, ap);

    // layer 1
    hgemm_kernel<128, 64><<<PADN / 64, 256>>>(ap, w1h, yp);
    gather1_kernel<128><<<WARP_GRID, 256>>>(yp, gb1, hp);
    gather2_ln_kernel<<<WARP_GRID, 256>>>(hp, ew1, eb1, lg1, lb1, ap);

    // layer 2
    hgemm_kernel<64, 128><<<PADN / 128, 256>>>(ap, w2h, yp);
    gather1_kernel<64><<<WARP_GRID, 256>>>(yp, gb2, hp);
    gather2_final_kernel<<<WARP_GRID, 256>>>(hp, ew2, eb2, out);

    pool_kernel<<<GG, 256>>>(out);
}